// round 4
// baseline (speedup 1.0000x reference)
#include <cuda_runtime.h>
#include <cuda_bf16.h>
#include <math.h>

// Problem constants (fixed by setup_inputs)
#define N_MAX   50000
#define E_MAX   400000
#define D_MAX   2048

// ---------------- device scratch (no allocations allowed) ----------------
__device__ float g_mean[(size_t)N_MAX * D_MAX];   // aggregated features
__device__ float g_h1  [(size_t)N_MAX * D_MAX];   // layer-1 activations
__device__ float g_h2  [(size_t)N_MAX * D_MAX];   // layer-2 activations
__device__ int   g_cnt   [N_MAX];
__device__ int   g_cursor[N_MAX];
__device__ int   g_off   [N_MAX + 1];
__device__ int   g_csr   [E_MAX];
__device__ float g_invdeg[N_MAX];

// ---------------- CSR build ----------------
__global__ void zero_kernel(int* cnt, int* cur, int n) {
    int i = blockIdx.x * blockDim.x + threadIdx.x;
    if (i < n) { cnt[i] = 0; cur[i] = 0; }
}

__global__ void count_kernel(const int* __restrict__ ei, int E, int* __restrict__ cnt) {
    int e = blockIdx.x * blockDim.x + threadIdx.x;
    if (e < E) atomicAdd(&cnt[ei[E + e]], 1);
}

// single-block exclusive scan over counts (n up to 50001 fine)
__global__ void scan_kernel(const int* __restrict__ cnt, int* __restrict__ off, int n) {
    __shared__ int wsum[32];
    __shared__ int carry_s;
    int tid = threadIdx.x, lane = tid & 31, wid = tid >> 5;
    if (tid == 0) carry_s = 0;
    __syncthreads();
    for (int base = 0; base < n; base += 1024) {
        int i = base + tid;
        int v = (i < n) ? cnt[i] : 0;
        int s = v;
        #pragma unroll
        for (int d = 1; d < 32; d <<= 1) {
            int t = __shfl_up_sync(0xffffffffu, s, d);
            if (lane >= d) s += t;
        }
        if (lane == 31) wsum[wid] = s;
        __syncthreads();
        if (wid == 0) {
            int w = wsum[lane];
            #pragma unroll
            for (int d = 1; d < 32; d <<= 1) {
                int t = __shfl_up_sync(0xffffffffu, w, d);
                if (lane >= d) w += t;
            }
            wsum[lane] = w;
        }
        __syncthreads();
        int add = (wid > 0) ? wsum[wid - 1] : 0;
        int incl = s + add;
        int c = carry_s;
        if (i < n) off[i] = c + incl - v;
        __syncthreads();
        if (tid == 1023) carry_s = c + incl;   // chunk total
        __syncthreads();
    }
    if (threadIdx.x == 0) off[n] = carry_s;
}

__global__ void scatter_kernel(const int* __restrict__ ei, int E,
                               const int* __restrict__ off, int* __restrict__ cur,
                               int* __restrict__ csr) {
    int e = blockIdx.x * blockDim.x + threadIdx.x;
    if (e < E) {
        int d = ei[E + e];
        int pos = off[d] + atomicAdd(&cur[d], 1);
        csr[pos] = ei[e];
    }
}

__global__ void invdeg_kernel(const int* __restrict__ cnt, float* __restrict__ invdeg, int n) {
    int i = blockIdx.x * blockDim.x + threadIdx.x;
    if (i < n) invdeg[i] = 1.0f / (float)max(cnt[i], 1);
}

// ---------------- mean aggregation via CSR gather ----------------
// grid: (N, d/(4*blockDim.x)); each thread owns one float4 of one node's output
__global__ void agg_mean_kernel(const float* __restrict__ X, float* __restrict__ out,
                                const int* __restrict__ off, const int* __restrict__ csr,
                                const float* __restrict__ invdeg, int d4) {
    int node = blockIdx.x;
    int f4 = blockIdx.y * blockDim.x + threadIdx.x;
    if (f4 >= d4) return;
    int s = off[node], e = off[node + 1];
    float4 acc = make_float4(0.f, 0.f, 0.f, 0.f);
    for (int i = s; i < e; i++) {
        int src = csr[i];
        float4 v = ((const float4*)(X + (size_t)src * (d4 * 4)))[f4];
        acc.x += v.x; acc.y += v.y; acc.z += v.z; acc.w += v.w;
    }
    float inv = invdeg[node];
    acc.x *= inv; acc.y *= inv; acc.z *= inv; acc.w *= inv;
    ((float4*)(out + (size_t)node * (d4 * 4)))[f4] = acc;
}

// ---------------- fused dual-GEMM: C = relu(A1@B1 + A2@B2 + bias) ----------------
#define BM 128
#define BN 128
#define BK 16
#define TM 8
#define TN 8

__global__ __launch_bounds__(256) void gemm_dual_kernel(
    const float* __restrict__ A1, const float* __restrict__ B1, int K1,
    const float* __restrict__ A2, const float* __restrict__ B2, int K2,
    const float* __restrict__ bias, float* __restrict__ C,
    int M, int Nc)
{
    __shared__ __align__(16) float As[BK][BM];   // transposed A tile
    __shared__ __align__(16) float Bs[BK][BN];

    int tid = threadIdx.x;
    int rowBase = blockIdx.y * BM;
    int colBase = blockIdx.x * BN;
    int tx = tid % 16, ty = tid / 16;

    float acc[TM][TN];
    #pragma unroll
    for (int i = 0; i < TM; i++)
        #pragma unroll
        for (int j = 0; j < TN; j++) acc[i][j] = 0.f;

    int aRow  = tid >> 2;        // 0..63 (two passes cover 128 rows)
    int aCol4 = tid & 3;         // float4 column within BK=16
    int bRow  = tid >> 5;        // 0..7 (two passes cover 16 rows)
    int bCol4 = tid & 31;        // float4 column within BN=128

    #pragma unroll
    for (int pass = 0; pass < 2; pass++) {
        const float* A = pass ? A2 : A1;
        const float* B = pass ? B2 : B1;
        int K = pass ? K2 : K1;
        for (int k0 = 0; k0 < K; k0 += BK) {
            // load A tile (clamped rows for M edge)
            #pragma unroll
            for (int r = 0; r < 2; r++) {
                int row = aRow + r * 64;
                int grow = rowBase + row;
                grow = grow < M ? grow : M - 1;
                float4 v = *(const float4*)(A + (size_t)grow * K + k0 + aCol4 * 4);
                As[aCol4 * 4 + 0][row] = v.x;
                As[aCol4 * 4 + 1][row] = v.y;
                As[aCol4 * 4 + 2][row] = v.z;
                As[aCol4 * 4 + 3][row] = v.w;
            }
            // load B tile
            #pragma unroll
            for (int r = 0; r < 2; r++) {
                int row = bRow + r * 8;
                float4 v = *(const float4*)(B + (size_t)(k0 + row) * Nc + colBase + bCol4 * 4);
                *(float4*)&Bs[row][bCol4 * 4] = v;
            }
            __syncthreads();

            #pragma unroll
            for (int kk = 0; kk < BK; kk++) {
                float ra[TM], rb[TN];
                #pragma unroll
                for (int i = 0; i < TM; i++) ra[i] = As[kk][ty * TM + i];
                #pragma unroll
                for (int j = 0; j < TN; j++) rb[j] = Bs[kk][tx * TN + j];
                #pragma unroll
                for (int i = 0; i < TM; i++)
                    #pragma unroll
                    for (int j = 0; j < TN; j++)
                        acc[i][j] += ra[i] * rb[j];
            }
            __syncthreads();
        }
    }

    // epilogue: bias + relu, vectorized stores
    #pragma unroll
    for (int i = 0; i < TM; i++) {
        int row = rowBase + ty * TM + i;
        if (row >= M) continue;
        #pragma unroll
        for (int j = 0; j < TN; j += 4) {
            int col = colBase + tx * TN + j;
            float4 v;
            v.x = fmaxf(acc[i][j + 0] + bias[col + 0], 0.f);
            v.y = fmaxf(acc[i][j + 1] + bias[col + 1], 0.f);
            v.z = fmaxf(acc[i][j + 2] + bias[col + 2], 0.f);
            v.w = fmaxf(acc[i][j + 3] + bias[col + 3], 0.f);
            *(float4*)(C + (size_t)row * Nc + col) = v;
        }
    }
}

// ---------------- row L2 normalize (in place) ----------------
__global__ void normalize_kernel(float* __restrict__ out, int d) {
    int row = blockIdx.x;
    float* p = out + (size_t)row * d;
    float s = 0.f;
    for (int i = threadIdx.x; i < d; i += blockDim.x) {
        float v = p[i];
        s += v * v;
    }
    // reduce 256 threads
    __shared__ float wsum[8];
    int lane = threadIdx.x & 31, wid = threadIdx.x >> 5;
    #pragma unroll
    for (int dlt = 16; dlt > 0; dlt >>= 1) s += __shfl_down_sync(0xffffffffu, s, dlt);
    if (lane == 0) wsum[wid] = s;
    __syncthreads();
    if (wid == 0) {
        s = (lane < 8) ? wsum[lane] : 0.f;
        #pragma unroll
        for (int dlt = 4; dlt > 0; dlt >>= 1) s += __shfl_down_sync(0xffffffffu, s, dlt);
        if (lane == 0) wsum[0] = s;
    }
    __syncthreads();
    float inv = 1.0f / fmaxf(sqrtf(wsum[0]), 1e-12f);
    for (int i = threadIdx.x; i < d; i += blockDim.x) p[i] *= inv;
}

// ---------------- launch ----------------
static void launch_agg(const float* X, float* out, const int* off, const int* csr,
                       const float* invdeg, int N, int d) {
    int d4 = d / 4;
    int threads = d4 < 256 ? d4 : 256;
    dim3 grid(N, d4 / threads);
    agg_mean_kernel<<<grid, threads>>>(X, out, off, csr, invdeg, d4);
}

extern "C" void kernel_launch(void* const* d_in, const int* in_sizes, int n_in,
                              void* d_out, int out_size) {
    const float* x   = (const float*)d_in[0];
    const int*   ei  = (const int*)d_in[2];          // int32: JAX x64 disabled
    const float* W1l = (const float*)d_in[3];
    const float* W1r = (const float*)d_in[4];
    const float* b1  = (const float*)d_in[5];
    const float* W2l = (const float*)d_in[6];
    const float* W2r = (const float*)d_in[7];
    const float* b2  = (const float*)d_in[8];
    const float* W3l = (const float*)d_in[9];
    const float* W3r = (const float*)d_in[10];
    const float* b3  = (const float*)d_in[11];
    float* out = (float*)d_out;

    const int N = in_sizes[0] / 128;
    const int E = in_sizes[2] / 2;

    float *mean, *h1, *h2, *invdeg;
    int *cnt, *cur, *off, *csr;
    cudaGetSymbolAddress((void**)&mean,   g_mean);
    cudaGetSymbolAddress((void**)&h1,     g_h1);
    cudaGetSymbolAddress((void**)&h2,     g_h2);
    cudaGetSymbolAddress((void**)&cnt,    g_cnt);
    cudaGetSymbolAddress((void**)&cur,    g_cursor);
    cudaGetSymbolAddress((void**)&off,    g_off);
    cudaGetSymbolAddress((void**)&csr,    g_csr);
    cudaGetSymbolAddress((void**)&invdeg, g_invdeg);

    // ---- CSR build ----
    zero_kernel<<<(N + 255) / 256, 256>>>(cnt, cur, N);
    count_kernel<<<(E + 255) / 256, 256>>>(ei, E, cnt);
    scan_kernel<<<1, 1024>>>(cnt, off, N);
    scatter_kernel<<<(E + 255) / 256, 256>>>(ei, E, off, cur, csr);
    invdeg_kernel<<<(N + 255) / 256, 256>>>(cnt, invdeg, N);

    // ---- Layer 1: d_in=128 -> 2048 ----
    launch_agg(x, mean, off, csr, invdeg, N, 128);
    {
        dim3 grid(2048 / BN, (N + BM - 1) / BM);
        gemm_dual_kernel<<<grid, 256>>>(mean, W1l, 128, x, W1r, 128, b1, h1, N, 2048);
    }
    // ---- Layer 2: 2048 -> 2048 ----
    launch_agg(h1, mean, off, csr, invdeg, N, 2048);
    {
        dim3 grid(2048 / BN, (N + BM - 1) / BM);
        gemm_dual_kernel<<<grid, 256>>>(mean, W2l, 2048, h1, W2r, 2048, b2, h2, N, 2048);
    }
    // ---- Layer 3: 2048 -> 1024 ----
    launch_agg(h2, mean, off, csr, invdeg, N, 2048);
    {
        dim3 grid(1024 / BN, (N + BM - 1) / BM);
        gemm_dual_kernel<<<grid, 256>>>(mean, W3l, 2048, h2, W3r, 2048, b3, out, N, 1024);
    }
    // ---- normalize ----
    normalize_kernel<<<N, 256>>>(out, 1024);
}

// round 5
// speedup vs baseline: 2.3221x; 2.3221x over previous
#include <cuda_runtime.h>
#include <cuda_bf16.h>
#include <math.h>
#include <stdint.h>

// Problem constants (fixed by setup_inputs)
#define N_MAX   50000
#define E_MAX   400000
#define D_MAX   2048

typedef __nv_bfloat16 bf16;

// ---------------- device scratch (no allocations allowed) ----------------
__device__ float g_h1[(size_t)N_MAX * D_MAX];          // layer-1 activations (fp32, for agg)
__device__ float g_h2[(size_t)N_MAX * D_MAX];          // layer-2 activations (fp32, for agg)
__device__ bf16  g_mh [(size_t)N_MAX * D_MAX];         // mean hi
__device__ bf16  g_ml [(size_t)N_MAX * D_MAX];         // mean lo
__device__ bf16  g_s0h[(size_t)N_MAX * D_MAX];         // act split buffers (ping)
__device__ bf16  g_s0l[(size_t)N_MAX * D_MAX];
__device__ bf16  g_s1h[(size_t)N_MAX * D_MAX];         // act split buffers (pong)
__device__ bf16  g_s1l[(size_t)N_MAX * D_MAX];
// weight splits, concatenated: W1l,W1r,W2l,W2r,W3l,W3r
#define W_TOTAL 13107200
__device__ bf16  g_wh[W_TOTAL];
__device__ bf16  g_wl[W_TOTAL];

__device__ int   g_cnt   [N_MAX];
__device__ int   g_cursor[N_MAX];
__device__ int   g_off   [N_MAX + 1];
__device__ int   g_csr   [E_MAX];
__device__ float g_invdeg[N_MAX];

// ---------------- CSR build ----------------
__global__ void zero_kernel(int* cnt, int* cur, int n) {
    int i = blockIdx.x * blockDim.x + threadIdx.x;
    if (i < n) { cnt[i] = 0; cur[i] = 0; }
}

__global__ void count_kernel(const int* __restrict__ ei, int E, int* __restrict__ cnt) {
    int e = blockIdx.x * blockDim.x + threadIdx.x;
    if (e < E) atomicAdd(&cnt[ei[E + e]], 1);
}

__global__ void scan_kernel(const int* __restrict__ cnt, int* __restrict__ off, int n) {
    __shared__ int wsum[32];
    __shared__ int carry_s;
    int tid = threadIdx.x, lane = tid & 31, wid = tid >> 5;
    if (tid == 0) carry_s = 0;
    __syncthreads();
    for (int base = 0; base < n; base += 1024) {
        int i = base + tid;
        int v = (i < n) ? cnt[i] : 0;
        int s = v;
        #pragma unroll
        for (int d = 1; d < 32; d <<= 1) {
            int t = __shfl_up_sync(0xffffffffu, s, d);
            if (lane >= d) s += t;
        }
        if (lane == 31) wsum[wid] = s;
        __syncthreads();
        if (wid == 0) {
            int w = wsum[lane];
            #pragma unroll
            for (int d = 1; d < 32; d <<= 1) {
                int t = __shfl_up_sync(0xffffffffu, w, d);
                if (lane >= d) w += t;
            }
            wsum[lane] = w;
        }
        __syncthreads();
        int add = (wid > 0) ? wsum[wid - 1] : 0;
        int incl = s + add;
        int c = carry_s;
        if (i < n) off[i] = c + incl - v;
        __syncthreads();
        if (tid == 1023) carry_s = c + incl;
        __syncthreads();
    }
    if (threadIdx.x == 0) off[n] = carry_s;
}

__global__ void scatter_kernel(const int* __restrict__ ei, int E,
                               const int* __restrict__ off, int* __restrict__ cur,
                               int* __restrict__ csr) {
    int e = blockIdx.x * blockDim.x + threadIdx.x;
    if (e < E) {
        int d = ei[E + e];
        int pos = off[d] + atomicAdd(&cur[d], 1);
        csr[pos] = ei[e];
    }
}

__global__ void invdeg_kernel(const int* __restrict__ cnt, float* __restrict__ invdeg, int n) {
    int i = blockIdx.x * blockDim.x + threadIdx.x;
    if (i < n) invdeg[i] = 1.0f / (float)max(cnt[i], 1);
}

// ---------------- generic fp32 -> (bf16 hi, bf16 lo) split ----------------
__global__ void split_kernel(const float* __restrict__ in, bf16* __restrict__ hi,
                             bf16* __restrict__ lo, int n) {
    int i = blockIdx.x * blockDim.x + threadIdx.x;
    if (i < n) {
        float v = in[i];
        bf16 h = __float2bfloat16(v);
        hi[i] = h;
        lo[i] = __float2bfloat16(v - __bfloat162float(h));
    }
}

// ---------------- mean aggregation via CSR gather, emitting hi/lo split ----------------
__global__ void agg_mean_split_kernel(const float* __restrict__ X,
                                      bf16* __restrict__ hi, bf16* __restrict__ lo,
                                      const int* __restrict__ off, const int* __restrict__ csr,
                                      const float* __restrict__ invdeg, int d4) {
    int node = blockIdx.x;
    int f4 = blockIdx.y * blockDim.x + threadIdx.x;
    if (f4 >= d4) return;
    int s = off[node], e = off[node + 1];
    float4 acc = make_float4(0.f, 0.f, 0.f, 0.f);
    for (int i = s; i < e; i++) {
        int src = csr[i];
        float4 v = ((const float4*)(X + (size_t)src * (d4 * 4)))[f4];
        acc.x += v.x; acc.y += v.y; acc.z += v.z; acc.w += v.w;
    }
    float inv = invdeg[node];
    float vs[4] = {acc.x * inv, acc.y * inv, acc.z * inv, acc.w * inv};
    bf16 hs[4], ls[4];
    #pragma unroll
    for (int j = 0; j < 4; j++) {
        hs[j] = __float2bfloat16(vs[j]);
        ls[j] = __float2bfloat16(vs[j] - __bfloat162float(hs[j]));
    }
    size_t base = (size_t)node * (d4 * 4) + (size_t)f4 * 4;
    ((__nv_bfloat162*)(hi + base))[0] = __nv_bfloat162(hs[0], hs[1]);
    ((__nv_bfloat162*)(hi + base))[1] = __nv_bfloat162(hs[2], hs[3]);
    ((__nv_bfloat162*)(lo + base))[0] = __nv_bfloat162(ls[0], ls[1]);
    ((__nv_bfloat162*)(lo + base))[1] = __nv_bfloat162(ls[2], ls[3]);
}

// ---------------- tensor-core fused GEMM ----------------
// C = relu( sum_{seg=0..5} A[seg] @ B[seg] + bias ), fp32 accum.
// Segments implement split-bf16 3-pass for two (A,B) product pairs.
// A[seg]: [M,K] bf16 row-major (lda=K). B[seg]: [K,Nc] bf16 row-major (ldb=Nc).
#define GBM 128
#define GBN 128
#define GBK 32
#define AS_STRIDE 40    // 32 + 8 halves (80B rows, conflict-free ldmatrix)
#define BS_STRIDE 136   // 128 + 8 halves (272B rows, conflict-free ldmatrix)

struct GemmArgs {
    const bf16* A[6];
    const bf16* B[6];
};

__device__ __forceinline__ uint32_t smem_u32(const void* p) {
    return (uint32_t)__cvta_generic_to_shared(p);
}
__device__ __forceinline__ void cp_async16(void* dst, const void* src) {
    asm volatile("cp.async.cg.shared.global [%0], [%1], 16;\n"
                 :: "r"(smem_u32(dst)), "l"(src));
}

__global__ __launch_bounds__(256) void gemm_mma_kernel(
    GemmArgs args, int K, const float* __restrict__ bias,
    float* __restrict__ C, bf16* __restrict__ Ch, bf16* __restrict__ Cl,
    int M, int Nc)
{
    __shared__ __align__(16) bf16 As[2][GBM * AS_STRIDE];
    __shared__ __align__(16) bf16 Bs[2][GBK * BS_STRIDE];

    const int tid = threadIdx.x;
    const int lane = tid & 31;
    const int wid = tid >> 5;
    const int wm = wid >> 2, wn = wid & 3;      // 2 x 4 warp grid
    const int mBase = wm * 64, nBase = wn * 32; // 64x32 warp tile
    const int rowBase = blockIdx.y * GBM;
    const int colBase = blockIdx.x * GBN;

    float acc[4][4][4];
    #pragma unroll
    for (int i = 0; i < 4; i++)
        #pragma unroll
        for (int j = 0; j < 4; j++)
            #pragma unroll
            for (int r = 0; r < 4; r++) acc[i][j][r] = 0.f;

    const int kIters = K / GBK;
    const int total = 6 * kIters;

    // stage loader
    auto load_tiles = [&](int s, int it) {
        int seg = it / kIters;
        int kk  = (it - seg * kIters) * GBK;
        const bf16* Aseg = args.A[seg];
        const bf16* Bseg = args.B[seg];
        #pragma unroll
        for (int i = 0; i < 2; i++) {
            int c = tid + i * 256;              // 512 chunks: 128 rows x 4
            int row = c >> 2, kc = (c & 3) * 8;
            int grow = rowBase + row; grow = grow < M ? grow : M - 1;
            cp_async16(&As[s][row * AS_STRIDE + kc], Aseg + (size_t)grow * K + kk + kc);
        }
        #pragma unroll
        for (int i = 0; i < 2; i++) {
            int c = tid + i * 256;              // 512 chunks: 32 rows x 16
            int row = c >> 4, nc = (c & 15) * 8;
            cp_async16(&Bs[s][row * BS_STRIDE + nc], Bseg + (size_t)(kk + row) * Nc + colBase + nc);
        }
    };

    load_tiles(0, 0);
    asm volatile("cp.async.commit_group;\n");

    const int mat = lane >> 3, r8 = lane & 7;

    for (int it = 0; it < total; it++) {
        if (it + 1 < total) {
            load_tiles((it + 1) & 1, it + 1);
            asm volatile("cp.async.commit_group;\n");
            asm volatile("cp.async.wait_group 1;\n");
        } else {
            asm volatile("cp.async.wait_group 0;\n");
        }
        __syncthreads();

        const bf16* as_ = As[it & 1];
        const bf16* bs_ = Bs[it & 1];
        #pragma unroll
        for (int ks = 0; ks < 2; ks++) {
            int k0 = ks * 16;
            uint32_t a[4][4];
            #pragma unroll
            for (int mi = 0; mi < 4; mi++) {
                int row = mBase + mi * 16 + (mat & 1) * 8 + r8;
                int col = k0 + (mat >> 1) * 8;
                uint32_t ad = smem_u32(as_ + row * AS_STRIDE + col);
                asm volatile("ldmatrix.sync.aligned.m8n8.x4.shared.b16 {%0,%1,%2,%3}, [%4];\n"
                    : "=r"(a[mi][0]), "=r"(a[mi][1]), "=r"(a[mi][2]), "=r"(a[mi][3]) : "r"(ad));
            }
            uint32_t b[4][2];
            #pragma unroll
            for (int bi = 0; bi < 2; bi++) {
                int row = k0 + (mat & 1) * 8 + r8;
                int col = nBase + bi * 16 + (mat >> 1) * 8;
                uint32_t bd = smem_u32(bs_ + row * BS_STRIDE + col);
                asm volatile("ldmatrix.sync.aligned.m8n8.x4.trans.shared.b16 {%0,%1,%2,%3}, [%4];\n"
                    : "=r"(b[2*bi][0]), "=r"(b[2*bi][1]), "=r"(b[2*bi+1][0]), "=r"(b[2*bi+1][1]) : "r"(bd));
            }
            #pragma unroll
            for (int mi = 0; mi < 4; mi++)
                #pragma unroll
                for (int ni = 0; ni < 4; ni++)
                    asm volatile("mma.sync.aligned.m16n8k16.row.col.f32.bf16.bf16.f32 "
                        "{%0,%1,%2,%3}, {%4,%5,%6,%7}, {%8,%9}, {%0,%1,%2,%3};\n"
                        : "+f"(acc[mi][ni][0]), "+f"(acc[mi][ni][1]),
                          "+f"(acc[mi][ni][2]), "+f"(acc[mi][ni][3])
                        : "r"(a[mi][0]), "r"(a[mi][1]), "r"(a[mi][2]), "r"(a[mi][3]),
                          "r"(b[ni][0]), "r"(b[ni][1]));
        }
        __syncthreads();
    }

    // epilogue: bias + relu; emit fp32 and optional hi/lo bf16 split
    const int lg = lane >> 2;
    const int lc = (lane & 3) * 2;
    #pragma unroll
    for (int mi = 0; mi < 4; mi++) {
        #pragma unroll
        for (int ni = 0; ni < 4; ni++) {
            int col = colBase + nBase + ni * 8 + lc;
            #pragma unroll
            for (int half = 0; half < 2; half++) {
                int row = rowBase + mBase + mi * 16 + lg + half * 8;
                if (row < M) {
                    float c0 = fmaxf(acc[mi][ni][half * 2 + 0] + bias[col + 0], 0.f);
                    float c1 = fmaxf(acc[mi][ni][half * 2 + 1] + bias[col + 1], 0.f);
                    size_t o = (size_t)row * Nc + col;
                    *(float2*)(C + o) = make_float2(c0, c1);
                    if (Ch) {
                        bf16 h0 = __float2bfloat16(c0), h1 = __float2bfloat16(c1);
                        *(__nv_bfloat162*)(Ch + o) = __nv_bfloat162(h0, h1);
                        *(__nv_bfloat162*)(Cl + o) = __nv_bfloat162(
                            __float2bfloat16(c0 - __bfloat162float(h0)),
                            __float2bfloat16(c1 - __bfloat162float(h1)));
                    }
                }
            }
        }
    }
}

// ---------------- row L2 normalize (in place) ----------------
__global__ void normalize_kernel(float* __restrict__ out, int d) {
    int row = blockIdx.x;
    float* p = out + (size_t)row * d;
    float s = 0.f;
    for (int i = threadIdx.x; i < d; i += blockDim.x) {
        float v = p[i];
        s += v * v;
    }
    __shared__ float wsum[8];
    int lane = threadIdx.x & 31, wid = threadIdx.x >> 5;
    #pragma unroll
    for (int dlt = 16; dlt > 0; dlt >>= 1) s += __shfl_down_sync(0xffffffffu, s, dlt);
    if (lane == 0) wsum[wid] = s;
    __syncthreads();
    if (wid == 0) {
        s = (lane < 8) ? wsum[lane] : 0.f;
        #pragma unroll
        for (int dlt = 4; dlt > 0; dlt >>= 1) s += __shfl_down_sync(0xffffffffu, s, dlt);
        if (lane == 0) wsum[0] = s;
    }
    __syncthreads();
    float inv = 1.0f / fmaxf(sqrtf(wsum[0]), 1e-12f);
    for (int i = threadIdx.x; i < d; i += blockDim.x) p[i] *= inv;
}

// ---------------- launch helpers ----------------
static void launch_agg(const float* X, bf16* hi, bf16* lo, const int* off, const int* csr,
                       const float* invdeg, int N, int d) {
    int d4 = d / 4;
    int threads = d4 < 256 ? d4 : 256;
    dim3 grid(N, d4 / threads);
    agg_mean_split_kernel<<<grid, threads>>>(X, hi, lo, off, csr, invdeg, d4);
}

extern "C" void kernel_launch(void* const* d_in, const int* in_sizes, int n_in,
                              void* d_out, int out_size) {
    const float* x   = (const float*)d_in[0];
    const int*   ei  = (const int*)d_in[2];          // int32: JAX x64 disabled
    const float* W1l = (const float*)d_in[3];
    const float* W1r = (const float*)d_in[4];
    const float* b1  = (const float*)d_in[5];
    const float* W2l = (const float*)d_in[6];
    const float* W2r = (const float*)d_in[7];
    const float* b2  = (const float*)d_in[8];
    const float* W3l = (const float*)d_in[9];
    const float* W3r = (const float*)d_in[10];
    const float* b3  = (const float*)d_in[11];
    float* out = (float*)d_out;

    const int N = in_sizes[0] / 128;
    const int E = in_sizes[2] / 2;

    float *h1, *h2, *invdeg;
    bf16 *mh, *ml, *s0h, *s0l, *s1h, *s1l, *wh, *wl;
    int *cnt, *cur, *off, *csr;
    cudaGetSymbolAddress((void**)&h1,  g_h1);
    cudaGetSymbolAddress((void**)&h2,  g_h2);
    cudaGetSymbolAddress((void**)&mh,  g_mh);
    cudaGetSymbolAddress((void**)&ml,  g_ml);
    cudaGetSymbolAddress((void**)&s0h, g_s0h);
    cudaGetSymbolAddress((void**)&s0l, g_s0l);
    cudaGetSymbolAddress((void**)&s1h, g_s1h);
    cudaGetSymbolAddress((void**)&s1l, g_s1l);
    cudaGetSymbolAddress((void**)&wh,  g_wh);
    cudaGetSymbolAddress((void**)&wl,  g_wl);
    cudaGetSymbolAddress((void**)&cnt, g_cnt);
    cudaGetSymbolAddress((void**)&cur, g_cursor);
    cudaGetSymbolAddress((void**)&off, g_off);
    cudaGetSymbolAddress((void**)&csr, g_csr);
    cudaGetSymbolAddress((void**)&invdeg, g_invdeg);

    // weight split offsets (elements)
    const size_t oW1l = 0,        nW1l = 128 * 2048;
    const size_t oW1r = 262144,   nW1r = 128 * 2048;
    const size_t oW2l = 524288,   nW2l = 2048 * 2048;
    const size_t oW2r = 4718592,  nW2r = 2048 * 2048;
    const size_t oW3l = 8912896,  nW3l = 2048 * 1024;
    const size_t oW3r = 11010048, nW3r = 2048 * 1024;

    // ---- CSR build ----
    zero_kernel<<<(N + 255) / 256, 256>>>(cnt, cur, N);
    count_kernel<<<(E + 255) / 256, 256>>>(ei, E, cnt);
    scan_kernel<<<1, 1024>>>(cnt, off, N);
    scatter_kernel<<<(E + 255) / 256, 256>>>(ei, E, off, cur, csr);
    invdeg_kernel<<<(N + 255) / 256, 256>>>(cnt, invdeg, N);

    // ---- splits: weights + input features ----
    split_kernel<<<((int)nW1l + 255) / 256, 256>>>(W1l, wh + oW1l, wl + oW1l, (int)nW1l);
    split_kernel<<<((int)nW1r + 255) / 256, 256>>>(W1r, wh + oW1r, wl + oW1r, (int)nW1r);
    split_kernel<<<((int)nW2l + 255) / 256, 256>>>(W2l, wh + oW2l, wl + oW2l, (int)nW2l);
    split_kernel<<<((int)nW2r + 255) / 256, 256>>>(W2r, wh + oW2r, wl + oW2r, (int)nW2r);
    split_kernel<<<((int)nW3l + 255) / 256, 256>>>(W3l, wh + oW3l, wl + oW3l, (int)nW3l);
    split_kernel<<<((int)nW3r + 255) / 256, 256>>>(W3r, wh + oW3r, wl + oW3r, (int)nW3r);
    split_kernel<<<(N * 128 + 255) / 256, 256>>>(x, s0h, s0l, N * 128);

    const int mTiles = (N + GBM - 1) / GBM;

    // ---- Layer 1: K=128 -> 2048 ----
    launch_agg(x, mh, ml, off, csr, invdeg, N, 128);
    {
        GemmArgs a;
        a.A[0] = mh;  a.A[1] = ml;  a.A[2] = mh;
        a.A[3] = s0h; a.A[4] = s0l; a.A[5] = s0h;
        a.B[0] = wh + oW1l; a.B[1] = wh + oW1l; a.B[2] = wl + oW1l;
        a.B[3] = wh + oW1r; a.B[4] = wh + oW1r; a.B[5] = wl + oW1r;
        dim3 grid(2048 / GBN, mTiles);
        gemm_mma_kernel<<<grid, 256>>>(a, 128, b1, h1, s1h, s1l, N, 2048);
    }
    // ---- Layer 2: K=2048 -> 2048 ----
    launch_agg(h1, mh, ml, off, csr, invdeg, N, 2048);
    {
        GemmArgs a;
        a.A[0] = mh;  a.A[1] = ml;  a.A[2] = mh;
        a.A[3] = s1h; a.A[4] = s1l; a.A[5] = s1h;
        a.B[0] = wh + oW2l; a.B[1] = wh + oW2l; a.B[2] = wl + oW2l;
        a.B[3] = wh + oW2r; a.B[4] = wh + oW2r; a.B[5] = wl + oW2r;
        dim3 grid(2048 / GBN, mTiles);
        gemm_mma_kernel<<<grid, 256>>>(a, 2048, b2, h2, s0h, s0l, N, 2048);
    }
    // ---- Layer 3: K=2048 -> 1024 ----
    launch_agg(h2, mh, ml, off, csr, invdeg, N, 2048);
    {
        GemmArgs a;
        a.A[0] = mh;  a.A[1] = ml;  a.A[2] = mh;
        a.A[3] = s0h; a.A[4] = s0l; a.A[5] = s0h;
        a.B[0] = wh + oW3l; a.B[1] = wh + oW3l; a.B[2] = wl + oW3l;
        a.B[3] = wh + oW3r; a.B[4] = wh + oW3r; a.B[5] = wl + oW3r;
        dim3 grid(1024 / GBN, mTiles);
        gemm_mma_kernel<<<grid, 256>>>(a, 2048, b3, out, (bf16*)nullptr, (bf16*)nullptr, N, 1024);
    }
    // ---- normalize ----
    normalize_kernel<<<N, 256>>>(out, 1024);
}